// round 10
// baseline (speedup 1.0000x reference)
#include <cuda_runtime.h>
#include <cstdint>

#define B_   64
#define S_   2048
#define RNN_ 1024
#define ATT_ 512
#define CTX_ 1024

#define NCHUNK 16
#define SCHUNK (S_ / NCHUNK)   // 128 rows per fused block
#define NGROUP 8               // pipeline groups of 8 rows
#define NGROUPS_PER_BLK (SCHUNK / NGROUP)  // 16

#define KSPLIT 16
#define KCHUNK (RNN_ / KSPLIT) // 64

// Scratch (no allocations allowed in kernel_launch)
__device__ float g_attn_part[KSPLIT * B_ * ATT_];
__device__ float g_attn_h[B_ * ATT_];
__device__ float g_escores[B_ * S_];        // UNNORMALIZED exp(score), masked -> 0
__device__ float g_bsum[B_ * NCHUNK];       // per-block e-sums (16 per batch row)
__device__ float g_partial[NCHUNK * B_ * CTX_];   // UNNORMALIZED e-weighted partials

// ---------------------------------------------------------------------------
// Kernel 1: split-K GEMM partials.  grid = (8 n-tiles, 16 k-chunks).
// ---------------------------------------------------------------------------
#define BM 64
#define BN 64
#define BK 32
__global__ __launch_bounds__(256) void attn_h_kernel(
    const float* __restrict__ h, const float* __restrict__ W) {
    __shared__ float As[BM][BK + 1];
    __shared__ float Bs[BN][BK + 1];
    const int a0 = blockIdx.x * BN;
    const int kbase = blockIdx.y * KCHUNK;
    const int tx = threadIdx.x & 15;
    const int ty = threadIdx.x >> 4;
    float acc[4][4] = {};

    for (int k0 = kbase; k0 < kbase + KCHUNK; k0 += BK) {
        for (int i = threadIdx.x; i < BM * BK; i += 256) {
            int r = i >> 5, c = i & 31;
            As[r][c] = h[r * RNN_ + k0 + c];
        }
        for (int i = threadIdx.x; i < BN * BK; i += 256) {
            int r = i >> 5, c = i & 31;
            Bs[r][c] = W[(a0 + r) * RNN_ + k0 + c];
        }
        __syncthreads();
#pragma unroll
        for (int k = 0; k < BK; k++) {
            float av[4], bv[4];
#pragma unroll
            for (int i = 0; i < 4; i++) av[i] = As[ty * 4 + i][k];
#pragma unroll
            for (int j = 0; j < 4; j++) bv[j] = Bs[tx * 4 + j][k];
#pragma unroll
            for (int i = 0; i < 4; i++)
#pragma unroll
                for (int j = 0; j < 4; j++)
                    acc[i][j] = fmaf(av[i], bv[j], acc[i][j]);
        }
        __syncthreads();
    }
    float* part = g_attn_part + (size_t)blockIdx.y * B_ * ATT_;
#pragma unroll
    for (int i = 0; i < 4; i++)
#pragma unroll
        for (int j = 0; j < 4; j++)
            part[(ty * 4 + i) * ATT_ + a0 + tx * 4 + j] = acc[i][j];
}

// ---------------------------------------------------------------------------
// Kernel 1b: reduce split-K partials + bias -> attn_h.
// ---------------------------------------------------------------------------
__global__ __launch_bounds__(256) void reduce_attn_kernel(
    const float* __restrict__ bias) {
    const int idx = blockIdx.x * 256 + threadIdx.x;
    const int a = idx & (ATT_ - 1);
    float s = bias[a];
#pragma unroll
    for (int k = 0; k < KSPLIT; k++)
        s += g_attn_part[(size_t)k * B_ * ATT_ + idx];
    g_attn_h[idx] = s;
}

// ---------------------------------------------------------------------------
// Accurate fast tanh: 1 - 2/(exp(2x)+1).
// ---------------------------------------------------------------------------
__device__ __forceinline__ float fast_tanh(float x) {
    float e = __expf(2.0f * x);
    return 1.0f - __fdividef(2.0f, e + 1.0f);
}

// ---------------------------------------------------------------------------
// Kernel 2 (FUSED, software-pipelined): block = (chunk, b) owns 128 rows.
// 16 groups x 8 rows, double-buffered e-scores:
//   iteration g: warps compute e of group g+1 (pc stream + MUFU) while the
//   block streams context of group g (DRAM) weighted by esc[g&1].
// One __syncthreads per group. Partials stay UNNORMALIZED (linearity);
// per-block e-sum -> g_bsum for the finalize kernel.
// mask read as promoted 4-byte bool (nonzero == True).
// ---------------------------------------------------------------------------
__global__ __launch_bounds__(256) void fused_kernel(
    const float4* __restrict__ pc, const float4* __restrict__ context,
    const uint32_t* __restrict__ mask,
    const float4* __restrict__ w_alpha, const float* __restrict__ b_alpha) {
    const int b = blockIdx.y;
    const int chunk = blockIdx.x;
    const int s0 = chunk * SCHUNK;
    const int t = threadIdx.x;
    const int lane = t & 31, widx = t >> 5;

    __shared__ float esc[2][NGROUP];   // e of the 8 rows of each buffered group
    __shared__ float wsum[8];

    const float4* ah = (const float4*)g_attn_h + b * (ATT_ / 4);
    const float ba = b_alpha[0];
    float esum = 0.0f;                 // lane 0 of each warp: sum of its e's

    // warp widx computes row (s0 + g*8 + widx) of group g
    auto compute_e = [&](int g, int buf) {
        const int r = s0 + g * NGROUP + widx;
        const float4* prow = pc + ((size_t)b * S_ + r) * (ATT_ / 4);
        float sum = 0.0f;
#pragma unroll
        for (int i = 0; i < 4; i++) {
            int idx = lane + i * 32;
            float4 p = __ldcs(prow + idx);
            float4 a = ah[idx];
            float4 w = w_alpha[idx];
            sum += fast_tanh(p.x + a.x) * w.x;
            sum += fast_tanh(p.y + a.y) * w.y;
            sum += fast_tanh(p.z + a.z) * w.z;
            sum += fast_tanh(p.w + a.w) * w.w;
        }
#pragma unroll
        for (int off = 16; off; off >>= 1)
            sum += __shfl_xor_sync(0xFFFFFFFFu, sum, off);
        if (lane == 0) {
            float e = (mask[b * S_ + r] != 0u) ? 0.0f : expf(sum + ba);
            esc[buf][widx] = e;
            g_escores[b * S_ + r] = e;
            esum += e;
        }
    };

    compute_e(0, 0);
    __syncthreads();

    float4 acc = make_float4(0.f, 0.f, 0.f, 0.f);
#pragma unroll
    for (int g = 0; g < NGROUPS_PER_BLK; g++) {
        if (g < NGROUPS_PER_BLK - 1)
            compute_e(g + 1, (g + 1) & 1);     // next group's e (pc + MUFU)
        const float4* cbase =
            context + ((size_t)b * S_ + s0 + g * NGROUP) * (CTX_ / 4);
#pragma unroll
        for (int s = 0; s < NGROUP; s++) {     // this group's ctx (DRAM)
            float4 v = __ldcs(cbase + (size_t)s * (CTX_ / 4) + t);
            float ww = esc[g & 1][s];
            acc.x = fmaf(ww, v.x, acc.x);
            acc.y = fmaf(ww, v.y, acc.y);
            acc.z = fmaf(ww, v.z, acc.z);
            acc.w = fmaf(ww, v.w, acc.w);
        }
        __syncthreads();
    }
    ((float4*)g_partial)[((size_t)chunk * B_ + b) * (CTX_ / 4) + t] = acc;

    if (lane == 0) wsum[widx] = esum;
    __syncthreads();
    if (t == 0) {
        float s = 0.0f;
#pragma unroll
        for (int i = 0; i < 8; i++) s += wsum[i];
        g_bsum[b * NCHUNK + chunk] = s;
    }
}

// ---------------------------------------------------------------------------
// Kernel 3 (finalize): grid (6, B) x 128.
//   total = fixed-order shuffle tree over the 16 bsums of row b.
//   parts 0-1: sum the 16 unnormalized partials for 128 float4-cols, scale.
//   parts 2-5: attn_out = e * inv over a 512-element slice.
// ---------------------------------------------------------------------------
__global__ __launch_bounds__(128) void finalize_kernel(
    float* __restrict__ wctx_out, float* __restrict__ attn_out) {
    const int b = blockIdx.y;
    const int part = blockIdx.x;
    const int t = threadIdx.x;

    __shared__ float total_sh;
    if (t < 32) {
        float v = (t < NCHUNK) ? g_bsum[b * NCHUNK + t] : 0.0f;
#pragma unroll
        for (int off = 16; off; off >>= 1)
            v += __shfl_xor_sync(0xFFFFFFFFu, v, off);
        if (t == 0) total_sh = v;
    }
    __syncthreads();
    const float total = total_sh;
    const float inv = (total > 0.0f) ? __fdividef(1.0f, total) : 0.0f;

    if (part < 2) {
        const int c4 = part * 128 + t;         // 0..255 float4 columns
        const float4* pp = (const float4*)g_partial;
        float4 acc = make_float4(0.f, 0.f, 0.f, 0.f);
#pragma unroll
        for (int c = 0; c < NCHUNK; c++) {
            float4 v = pp[((size_t)c * B_ + b) * (CTX_ / 4) + c4];
            acc.x += v.x; acc.y += v.y; acc.z += v.z; acc.w += v.w;
        }
        acc.x *= inv; acc.y *= inv; acc.z *= inv; acc.w *= inv;
        ((float4*)wctx_out)[b * (CTX_ / 4) + c4] = acc;
    } else {
        const int p = part - 2;                // 0..3, 512 elems each
        const float* row = g_escores + b * S_;
        float* out = attn_out + b * S_;
#pragma unroll
        for (int i = 0; i < 4; i++) {
            int s = p * 512 + i * 128 + t;
            out[s] = (total > 0.0f) ? row[s] * inv : (1.0f / S_);
        }
    }
}

// ---------------------------------------------------------------------------
extern "C" void kernel_launch(void* const* d_in, const int* in_sizes, int n_in,
                              void* d_out, int out_size) {
    const float*    h    = (const float*)d_in[0];
    const float*    pc   = (const float*)d_in[1];
    const float*    ctx  = (const float*)d_in[2];
    const uint32_t* mask = (const uint32_t*)d_in[3];
    const float*    W    = (const float*)d_in[4];
    const float*    bh   = (const float*)d_in[5];
    const float*    wa   = (const float*)d_in[6];
    const float*    ba   = (const float*)d_in[7];

    float* out      = (float*)d_out;
    float* wctx_out = out;               // [B, CTX]
    float* attn_out = out + B_ * CTX_;   // [B, S]

    attn_h_kernel<<<dim3(ATT_ / BN, KSPLIT), 256>>>(h, W);
    reduce_attn_kernel<<<(B_ * ATT_) / 256, 256>>>(bh);
    fused_kernel<<<dim3(NCHUNK, B_), 256>>>((const float4*)pc,
                                            (const float4*)ctx, mask,
                                            (const float4*)wa, ba);
    finalize_kernel<<<dim3(6, B_), 128>>>(wctx_out, attn_out);
}

// round 11
// speedup vs baseline: 1.2119x; 1.2119x over previous
#include <cuda_runtime.h>
#include <cstdint>

#define B_   64
#define S_   2048
#define RNN_ 1024
#define ATT_ 512
#define CTX_ 1024

#define NCHUNK 32
#define SCHUNK (S_ / NCHUNK)   // 64 rows per fused block
#define NGROUP 8               // pipeline groups of 8 rows
#define NGROUPS_PER_BLK (SCHUNK / NGROUP)  // 8

#define KSPLIT 16
#define KCHUNK (RNN_ / KSPLIT) // 64

// Scratch (no allocations allowed in kernel_launch)
__device__ float g_attn_part[KSPLIT * B_ * ATT_];
__device__ float g_attn_h[B_ * ATT_];
__device__ float g_escores[B_ * S_];        // UNNORMALIZED exp(score), masked -> 0
__device__ float g_bsum[B_ * NCHUNK];       // per-block e-sums (32 per batch row)
__device__ float g_partial[NCHUNK * B_ * CTX_];   // UNNORMALIZED e-weighted partials

// ---------------------------------------------------------------------------
// Kernel 1: split-K GEMM partials.  grid = (8 n-tiles, 16 k-chunks).
// ---------------------------------------------------------------------------
#define BM 64
#define BN 64
#define BK 32
__global__ __launch_bounds__(256) void attn_h_kernel(
    const float* __restrict__ h, const float* __restrict__ W) {
    __shared__ float As[BM][BK + 1];
    __shared__ float Bs[BN][BK + 1];
    const int a0 = blockIdx.x * BN;
    const int kbase = blockIdx.y * KCHUNK;
    const int tx = threadIdx.x & 15;
    const int ty = threadIdx.x >> 4;
    float acc[4][4] = {};

    for (int k0 = kbase; k0 < kbase + KCHUNK; k0 += BK) {
        for (int i = threadIdx.x; i < BM * BK; i += 256) {
            int r = i >> 5, c = i & 31;
            As[r][c] = h[r * RNN_ + k0 + c];
        }
        for (int i = threadIdx.x; i < BN * BK; i += 256) {
            int r = i >> 5, c = i & 31;
            Bs[r][c] = W[(a0 + r) * RNN_ + k0 + c];
        }
        __syncthreads();
#pragma unroll
        for (int k = 0; k < BK; k++) {
            float av[4], bv[4];
#pragma unroll
            for (int i = 0; i < 4; i++) av[i] = As[ty * 4 + i][k];
#pragma unroll
            for (int j = 0; j < 4; j++) bv[j] = Bs[tx * 4 + j][k];
#pragma unroll
            for (int i = 0; i < 4; i++)
#pragma unroll
                for (int j = 0; j < 4; j++)
                    acc[i][j] = fmaf(av[i], bv[j], acc[i][j]);
        }
        __syncthreads();
    }
    float* part = g_attn_part + (size_t)blockIdx.y * B_ * ATT_;
#pragma unroll
    for (int i = 0; i < 4; i++)
#pragma unroll
        for (int j = 0; j < 4; j++)
            part[(ty * 4 + i) * ATT_ + a0 + tx * 4 + j] = acc[i][j];
}

// ---------------------------------------------------------------------------
// Kernel 1b: reduce split-K partials + bias -> attn_h.
// ---------------------------------------------------------------------------
__global__ __launch_bounds__(256) void reduce_attn_kernel(
    const float* __restrict__ bias) {
    const int idx = blockIdx.x * 256 + threadIdx.x;
    const int a = idx & (ATT_ - 1);
    float s = bias[a];
#pragma unroll
    for (int k = 0; k < KSPLIT; k++)
        s += g_attn_part[(size_t)k * B_ * ATT_ + idx];
    g_attn_h[idx] = s;
}

// ---------------------------------------------------------------------------
// Accurate fast tanh: 1 - 2/(exp(2x)+1).
// ---------------------------------------------------------------------------
__device__ __forceinline__ float fast_tanh(float x) {
    float e = __expf(2.0f * x);
    return 1.0f - __fdividef(2.0f, e + 1.0f);
}

// ---------------------------------------------------------------------------
// Kernel 2 (FUSED, software-pipelined): block = (chunk, b) owns 64 rows.
// 8 groups x 8 rows, double-buffered e-scores:
//   iteration g: warps compute e of group g+1 (pc stream + MUFU) while the
//   block streams context of group g (DRAM) weighted by esc[g&1].
// One __syncthreads per group. Partials stay UNNORMALIZED (linearity);
// per-block e-sum -> g_bsum for the finalize kernel.
// mask read as promoted 4-byte bool (nonzero == True).
// ---------------------------------------------------------------------------
__global__ __launch_bounds__(256) void fused_kernel(
    const float4* __restrict__ pc, const float4* __restrict__ context,
    const uint32_t* __restrict__ mask,
    const float4* __restrict__ w_alpha, const float* __restrict__ b_alpha) {
    const int b = blockIdx.y;
    const int chunk = blockIdx.x;
    const int s0 = chunk * SCHUNK;
    const int t = threadIdx.x;
    const int lane = t & 31, widx = t >> 5;

    __shared__ float esc[2][NGROUP];   // e of the 8 rows of each buffered group
    __shared__ float wsum[8];

    const float4* ah = (const float4*)g_attn_h + b * (ATT_ / 4);
    const float ba = b_alpha[0];
    float esum = 0.0f;                 // lane 0 of each warp: sum of its e's

    // warp widx computes row (s0 + g*8 + widx) of group g
    auto compute_e = [&](int g, int buf) {
        const int r = s0 + g * NGROUP + widx;
        const float4* prow = pc + ((size_t)b * S_ + r) * (ATT_ / 4);
        float sum = 0.0f;
#pragma unroll
        for (int i = 0; i < 4; i++) {
            int idx = lane + i * 32;
            float4 p = __ldcs(prow + idx);
            float4 a = ah[idx];
            float4 w = w_alpha[idx];
            sum += fast_tanh(p.x + a.x) * w.x;
            sum += fast_tanh(p.y + a.y) * w.y;
            sum += fast_tanh(p.z + a.z) * w.z;
            sum += fast_tanh(p.w + a.w) * w.w;
        }
#pragma unroll
        for (int off = 16; off; off >>= 1)
            sum += __shfl_xor_sync(0xFFFFFFFFu, sum, off);
        if (lane == 0) {
            float e = (mask[b * S_ + r] != 0u) ? 0.0f : expf(sum + ba);
            esc[buf][widx] = e;
            g_escores[b * S_ + r] = e;
            esum += e;
        }
    };

    compute_e(0, 0);
    __syncthreads();

    float4 acc = make_float4(0.f, 0.f, 0.f, 0.f);
#pragma unroll
    for (int g = 0; g < NGROUPS_PER_BLK; g++) {
        if (g < NGROUPS_PER_BLK - 1)
            compute_e(g + 1, (g + 1) & 1);     // next group's e (pc + MUFU)
        const float4* cbase =
            context + ((size_t)b * S_ + s0 + g * NGROUP) * (CTX_ / 4);
#pragma unroll
        for (int s = 0; s < NGROUP; s++) {     // this group's ctx (DRAM)
            float4 v = __ldcs(cbase + (size_t)s * (CTX_ / 4) + t);
            float ww = esc[g & 1][s];
            acc.x = fmaf(ww, v.x, acc.x);
            acc.y = fmaf(ww, v.y, acc.y);
            acc.z = fmaf(ww, v.z, acc.z);
            acc.w = fmaf(ww, v.w, acc.w);
        }
        __syncthreads();
    }
    ((float4*)g_partial)[((size_t)chunk * B_ + b) * (CTX_ / 4) + t] = acc;

    if (lane == 0) wsum[widx] = esum;
    __syncthreads();
    if (t == 0) {
        float s = 0.0f;
#pragma unroll
        for (int i = 0; i < 8; i++) s += wsum[i];
        g_bsum[b * NCHUNK + chunk] = s;
    }
}

// ---------------------------------------------------------------------------
// Kernel 3 (finalize): grid (6, B) x 256.
//   total = fixed-order shuffle tree over the 32 bsums of row b.
//   parts 0-1: wctx reduce, 128 float4-cols per part, TWO threads per column
//              (each sums a fixed half of the 32 chunks; deterministic
//              low+high combine via smem), scaled by inv.
//   parts 2-5: attn_out = e * inv over a 512-element slice.
// ---------------------------------------------------------------------------
__global__ __launch_bounds__(256) void finalize_kernel(
    float* __restrict__ wctx_out, float* __restrict__ attn_out) {
    const int b = blockIdx.y;
    const int part = blockIdx.x;
    const int t = threadIdx.x;

    __shared__ float total_sh;
    if (t < 32) {
        float v = g_bsum[b * NCHUNK + t];
#pragma unroll
        for (int off = 16; off; off >>= 1)
            v += __shfl_xor_sync(0xFFFFFFFFu, v, off);
        if (t == 0) total_sh = v;
    }
    __syncthreads();
    const float total = total_sh;
    const float inv = (total > 0.0f) ? __fdividef(1.0f, total) : 0.0f;

    if (part < 2) {
        __shared__ float4 hi_sh[128];
        const int col = t >> 1;                // 0..127 within part
        const int half = t & 1;                // which 16-chunk half
        const int c4 = part * 128 + col;       // global float4 column 0..255
        const float4* pp = (const float4*)g_partial;
        float4 acc = make_float4(0.f, 0.f, 0.f, 0.f);
#pragma unroll
        for (int i = 0; i < 16; i++) {
            int c = half * 16 + i;
            float4 v = pp[((size_t)c * B_ + b) * (CTX_ / 4) + c4];
            acc.x += v.x; acc.y += v.y; acc.z += v.z; acc.w += v.w;
        }
        if (half == 1) hi_sh[col] = acc;
        __syncthreads();
        if (half == 0) {
            float4 hv = hi_sh[col];            // fixed order: low + high
            acc.x = (acc.x + hv.x) * inv;
            acc.y = (acc.y + hv.y) * inv;
            acc.z = (acc.z + hv.z) * inv;
            acc.w = (acc.w + hv.w) * inv;
            ((float4*)wctx_out)[b * (CTX_ / 4) + c4] = acc;
        }
    } else {
        const int p = part - 2;                // 0..3, 512 elems each
        const float* row = g_escores + b * S_;
        float* out = attn_out + b * S_;
#pragma unroll
        for (int i = 0; i < 2; i++) {
            int s = p * 512 + i * 256 + t;
            out[s] = (total > 0.0f) ? row[s] * inv : (1.0f / S_);
        }
    }
}

// ---------------------------------------------------------------------------
extern "C" void kernel_launch(void* const* d_in, const int* in_sizes, int n_in,
                              void* d_out, int out_size) {
    const float*    h    = (const float*)d_in[0];
    const float*    pc   = (const float*)d_in[1];
    const float*    ctx  = (const float*)d_in[2];
    const uint32_t* mask = (const uint32_t*)d_in[3];
    const float*    W    = (const float*)d_in[4];
    const float*    bh   = (const float*)d_in[5];
    const float*    wa   = (const float*)d_in[6];
    const float*    ba   = (const float*)d_in[7];

    float* out      = (float*)d_out;
    float* wctx_out = out;               // [B, CTX]
    float* attn_out = out + B_ * CTX_;   // [B, S]

    attn_h_kernel<<<dim3(ATT_ / BN, KSPLIT), 256>>>(h, W);
    reduce_attn_kernel<<<(B_ * ATT_) / 256, 256>>>(bh);
    fused_kernel<<<dim3(NCHUNK, B_), 256>>>((const float4*)pc,
                                            (const float4*)ctx, mask,
                                            (const float4*)wa, ba);
    finalize_kernel<<<dim3(6, B_), 256>>>(wctx_out, attn_out);
}